// round 11
// baseline (speedup 1.0000x reference)
#include <cuda_runtime.h>
#include <cuda_bf16.h>
#include <cstdint>
#include <cstddef>

// Problem constants
#define BATCH   32
#define TSTEPS  2048
#define INDIM   256
#define HDIM    256
#define GDIM    768            // 3*H
#define OUTDIM  256

// Scratch for xg = x @ W_i + bias : (B*T, 3H) fp32 = 192 MB
__device__ float g_xg[(size_t)BATCH * TSTEPS * GDIM];

// ---------------------------------------------------------------------------
// Helpers (all asm forms proven on sm_100a in passing rounds)
// ---------------------------------------------------------------------------
__device__ __forceinline__ uint32_t smem_u32(const void* p) {
    uint32_t a;
    asm("{ .reg .u64 t; cvta.to.shared.u64 t, %1; cvt.u32.u64 %0, t; }"
        : "=r"(a) : "l"(p));
    return a;
}

__device__ __forceinline__ void cluster_arrive_() {
    asm volatile("barrier.cluster.arrive.aligned;" ::: "memory");
}
__device__ __forceinline__ void cluster_wait_() {
    asm volatile("barrier.cluster.wait.aligned;" ::: "memory");
}

// overflow-safe fast sigmoid / tanh (MUFU-only)
__device__ __forceinline__ float sigmoid_(float x) {
    float e = __expf(-x);
    return __fdividef(1.0f, 1.0f + e);
}
__device__ __forceinline__ float tanh_(float x) {
    float e = __expf(2.0f * x);
    return 1.0f - __fdividef(2.0f, e + 1.0f);
}

// ---------------------------------------------------------------------------
// Kernel 1: xg = x @ W_i + bias    (M=65536, N=768, K=256)
// NEW: BM=128, BN=128, BK=8, 256 threads, 8x8 outputs/thread.
// FFMA fraction per kk: 64 FFMA vs 4 LDS.128 -> fma-pipe-bound (~75-80%).
// ---------------------------------------------------------------------------
__global__ __launch_bounds__(256)
void gemm_xg_kernel(const float* __restrict__ X,
                    const float* __restrict__ Wi,
                    const float* __restrict__ bias)
{
    __shared__ __align__(16) float As[8][128];   // transposed A tile (k-major)
    __shared__ __align__(16) float Bs[8][128];

    const int bm = blockIdx.x * 128;
    const int bn = blockIdx.y * 128;
    const int tid = threadIdx.x;
    const int tx = tid & 15;       // N direction (8 cols)
    const int ty = tid >> 4;       // M direction (8 rows)

    float acc[8][8];
#pragma unroll
    for (int i = 0; i < 8; ++i)
#pragma unroll
        for (int j = 0; j < 8; ++j) acc[i][j] = 0.0f;

    for (int k0 = 0; k0 < INDIM; k0 += 8) {
        // Load A tile 128x8 (1 float4/thread), store transposed
        {
            int row = tid >> 1;            // 0..127
            int k4  = (tid & 1) << 2;      // 0 or 4
            float4 v = *reinterpret_cast<const float4*>(
                X + (size_t)(bm + row) * INDIM + k0 + k4);
            As[k4 + 0][row] = v.x;
            As[k4 + 1][row] = v.y;
            As[k4 + 2][row] = v.z;
            As[k4 + 3][row] = v.w;
        }
        // Load B tile 8x128 (1 float4/thread)
        {
            int kr = tid >> 5;             // 0..7
            int c4 = (tid & 31) << 2;      // 0..124
            float4 v = *reinterpret_cast<const float4*>(
                Wi + (size_t)(k0 + kr) * GDIM + bn + c4);
            *reinterpret_cast<float4*>(&Bs[kr][c4]) = v;
        }
        __syncthreads();

#pragma unroll
        for (int kk = 0; kk < 8; ++kk) {
            float4 a0 = *reinterpret_cast<const float4*>(&As[kk][ty * 8]);
            float4 a1 = *reinterpret_cast<const float4*>(&As[kk][ty * 8 + 4]);
            float4 b0 = *reinterpret_cast<const float4*>(&Bs[kk][tx * 8]);
            float4 b1 = *reinterpret_cast<const float4*>(&Bs[kk][tx * 8 + 4]);
            float a[8] = {a0.x, a0.y, a0.z, a0.w, a1.x, a1.y, a1.z, a1.w};
            float bb[8] = {b0.x, b0.y, b0.z, b0.w, b1.x, b1.y, b1.z, b1.w};
#pragma unroll
            for (int i = 0; i < 8; ++i)
#pragma unroll
                for (int j = 0; j < 8; ++j)
                    acc[i][j] = fmaf(a[i], bb[j], acc[i][j]);
        }
        __syncthreads();
    }

    float4 bv0 = *reinterpret_cast<const float4*>(bias + bn + tx * 8);
    float4 bv1 = *reinterpret_cast<const float4*>(bias + bn + tx * 8 + 4);
#pragma unroll
    for (int i = 0; i < 8; ++i) {
        int row = bm + ty * 8 + i;
        float4 o0, o1;
        o0.x = acc[i][0] + bv0.x;
        o0.y = acc[i][1] + bv0.y;
        o0.z = acc[i][2] + bv0.z;
        o0.w = acc[i][3] + bv0.w;
        o1.x = acc[i][4] + bv1.x;
        o1.y = acc[i][5] + bv1.y;
        o1.z = acc[i][6] + bv1.z;
        o1.w = acc[i][7] + bv1.w;
        float* op = g_xg + (size_t)row * GDIM + bn + tx * 8;
        *reinterpret_cast<float4*>(op)     = o0;
        *reinterpret_cast<float4*>(op + 4) = o1;
    }
}

// ---------------------------------------------------------------------------
// Kernel 2: GRU recurrence — R10's measured-best version, unchanged except
// h_old LDS issued before the dot loop (off the gate-phase critical chain).
// Grid = 128 CTAs, cluster of 4 per batch row, 384 threads/CTA.
// ---------------------------------------------------------------------------
__global__ __launch_bounds__(384, 1) __cluster_dims__(4, 1, 1)
void gru_rec_kernel(const float* __restrict__ Wh,
                    float* __restrict__ states)
{
    __shared__ __align__(16) float h_sm[2][HDIM];   // buf1 = buf0 + 1024B
    __shared__ __align__(16) float g_sm[192];

    uint32_t crank;
    asm("mov.u32 %0, %%cluster_ctarank;" : "=r"(crank));
    const int b      = blockIdx.x >> 2;
    const int tid    = threadIdx.x;
    const int half   = tid & 1;       // K half: [0,128) or [128,256)
    const int pairId = tid >> 1;      // 0..191
    const int gate   = pairId >> 6;   // 0..2
    const int jj     = pairId & 63;   // H index within chunk
    const int col    = gate * HDIM + (int)crank * 64 + jj;  // W_h column

    // ---- W half-column in 128 regs, granule order rotated by `half` ----
    float W[128];
    {
#pragma unroll
        for (int g = 0; g < 32; ++g) {
            int rho = (g + half) & 31;
            int kbase = half * 128 + rho * 4;
#pragma unroll
            for (int e = 0; e < 4; ++e)
                W[g * 4 + e] = Wh[(size_t)(kbase + e) * GDIM + col];
        }
    }

    // ---- init ----
    if (tid < HDIM) { h_sm[0][tid] = 0.0f; h_sm[1][tid] = 0.0f; }
    __syncthreads();
    cluster_arrive_();
    cluster_wait_();   // zeros visible cluster-wide

    // ---- gate threads (tid<64): remote h slots in all 4 ranks (buf0) ----
    uint32_t dst0[4];
    {
        uint32_t l0 = smem_u32(&h_sm[0][(int)crank * 64 + (tid & 63)]);
#pragma unroll
        for (int rk = 0; rk < 4; ++rk) {
            asm("mapa.shared::cluster.u32 %0, %1, %2;"
                : "=r"(dst0[rk]) : "r"(l0), "r"(rk));
        }
    }

    // ---- xg: 2-step-ahead register prefetch (gate threads) ----
    const float* xgp = g_xg + (size_t)b * TSTEPS * GDIM + (int)crank * 64 + (tid & 63);
    float x0r = 0.f, x0z = 0.f, x0n = 0.f;   // even t
    float x1r = 0.f, x1z = 0.f, x1n = 0.f;   // odd t
    if (tid < 64) {
        x0r = xgp[0];
        x0z = xgp[HDIM];
        x0n = xgp[2 * HDIM];
        const float* x1 = xgp + GDIM;
        x1r = x1[0];
        x1z = x1[HDIM];
        x1n = x1[2 * HDIM];
    }

    const size_t PL = (size_t)TSTEPS * HDIM;
    float* sp0 = states + (size_t)b * 4 * PL + (int)crank * 64 + (tid & 63);

    for (int t = 0; t < TSTEPS; ++t) {
        const int cur = t & 1;
        const int nxt = cur ^ 1;
        const bool last = (t == TSTEPS - 1);

        // gate threads: issue h_old load before the dot (hides 29-cyc LDS)
        float h_old = 0.f;
        if (tid < 64) h_old = h_sm[cur][(int)crank * 64 + tid];

        // ---- dot over my K half (rotated conflict-free LDS.128) ----
        const float4* hp = reinterpret_cast<const float4*>(&h_sm[cur][half * 128]);
        float a0 = 0.f, a1 = 0.f, a2 = 0.f, a3 = 0.f;
#pragma unroll
        for (int g = 0; g < 32; ++g) {
            int rho = (g + half) & 31;
            float4 hv = hp[rho];
            a0 = fmaf(W[g * 4 + 0], hv.x, a0);
            a1 = fmaf(W[g * 4 + 1], hv.y, a1);
            a2 = fmaf(W[g * 4 + 2], hv.z, a2);
            a3 = fmaf(W[g * 4 + 3], hv.w, a3);
        }
        float s = (a0 + a1) + (a2 + a3);
        s += __shfl_xor_sync(0xffffffffu, s, 1);   // combine the two halves

        if (half == 0) g_sm[pairId] = s;           // raw partial
        __syncthreads();                           // partials visible

        // ---- gates on 64 threads ----
        float r = 0.f, z = 0.f, n = 0.f, hn = 0.f;
        if (tid < 64) {
            float s0 = g_sm[tid];
            float s1 = g_sm[64 + tid];
            float s2 = g_sm[128 + tid];
            float xr = cur ? x1r : x0r;
            float xz = cur ? x1z : x0z;
            float xn = cur ? x1n : x0n;
            r  = sigmoid_(xr + s0);
            z  = sigmoid_(xz + s1);
            float gg = xn + s2;
            n  = tanh_(fmaf(r, gg, gg));           // tanh(gn + r*gn)
            hn = fmaf(z, h_old - n, n);            // (1-z)n + z h

            if (!last) {
                const uint32_t boff = (uint32_t)nxt * 1024u;
#pragma unroll
                for (int rk = 0; rk < 4; ++rk) {
                    asm volatile("st.shared::cluster.f32 [%0], %1;"
                                 :: "r"(dst0[rk] + boff), "f"(hn) : "memory");
                }
            }
        }

        if (!last) cluster_arrive_();   // release: orders the stores above

        // ---- overlapped with barrier: states STG + xg prefetch (t+2) ----
        if (tid < 64) {
            float* sp = sp0 + (size_t)t * HDIM;
            sp[0]      = hn;
            sp[PL]     = r;
            sp[2 * PL] = z;
            sp[3 * PL] = n;
            if (t + 2 < TSTEPS) {
                const float* xq = xgp + (size_t)(t + 2) * GDIM;
                if (cur) { x1r = xq[0]; x1z = xq[HDIM]; x1n = xq[2 * HDIM]; }
                else     { x0r = xq[0]; x0z = xq[HDIM]; x0n = xq[2 * HDIM]; }
            }
        }

        if (!last) cluster_wait_();     // acquire: peers' h writes visible
    }
}

// ---------------------------------------------------------------------------
// Kernel 3: output = h_last @ fc_w + fc_b   (32 x 256, K=256) — tiny
// ---------------------------------------------------------------------------
__global__ __launch_bounds__(256)
void fc_kernel(const float* __restrict__ states,
               const float* __restrict__ fc_w,
               const float* __restrict__ fc_b,
               float* __restrict__ out)
{
    const int b = blockIdx.x;
    const int o = threadIdx.x;
    const float* h = states + (((size_t)b * 4 + 0) * TSTEPS + (TSTEPS - 1)) * HDIM;
    float a0 = 0.f, a1 = 0.f, a2 = 0.f, a3 = 0.f;
#pragma unroll 8
    for (int k = 0; k < HDIM; k += 4) {
        a0 = fmaf(h[k + 0], fc_w[(size_t)(k + 0) * OUTDIM + o], a0);
        a1 = fmaf(h[k + 1], fc_w[(size_t)(k + 1) * OUTDIM + o], a1);
        a2 = fmaf(h[k + 2], fc_w[(size_t)(k + 2) * OUTDIM + o], a2);
        a3 = fmaf(h[k + 3], fc_w[(size_t)(k + 3) * OUTDIM + o], a3);
    }
    out[(size_t)b * OUTDIM + o] = (a0 + a1) + (a2 + a3) + fc_b[o];
}

// ---------------------------------------------------------------------------
// Launch
// ---------------------------------------------------------------------------
extern "C" void kernel_launch(void* const* d_in, const int* in_sizes, int n_in,
                              void* d_out, int out_size)
{
    const float* x    = (const float*)d_in[0];
    const float* Wi   = (const float*)d_in[1];
    const float* Wh   = (const float*)d_in[2];
    const float* bias = (const float*)d_in[3];
    const float* fcw  = (const float*)d_in[4];
    const float* fcb  = (const float*)d_in[5];

    float* out    = (float*)d_out;                 // (32, 256)
    float* states = out + (size_t)BATCH * OUTDIM;  // (32, 4, 2048, 256)

    dim3 ggrid((BATCH * TSTEPS) / 128, GDIM / 128);
    gemm_xg_kernel<<<ggrid, 256>>>(x, Wi, bias);

    gru_rec_kernel<<<BATCH * 4, 384>>>(Wh, states);

    fc_kernel<<<BATCH, 256>>>(states, fcw, fcb, out);
}

// round 12
// speedup vs baseline: 1.2221x; 1.2221x over previous
#include <cuda_runtime.h>
#include <cuda_bf16.h>
#include <cstdint>
#include <cstddef>

// Problem constants
#define BATCH   32
#define TSTEPS  2048
#define INDIM   256
#define HDIM    256
#define GDIM    768            // 3*H
#define OUTDIM  256

// Scratch for xg = x @ W_i + bias : (B*T, 3H) fp32 = 192 MB
__device__ float g_xg[(size_t)BATCH * TSTEPS * GDIM];

// ---------------------------------------------------------------------------
// Helpers
// ---------------------------------------------------------------------------
__device__ __forceinline__ uint32_t smem_u32(const void* p) {
    uint32_t a;
    asm("{ .reg .u64 t; cvta.to.shared.u64 t, %1; cvt.u32.u64 %0, t; }"
        : "=r"(a) : "l"(p));
    return a;
}

__device__ __forceinline__ void cluster_arrive_() {
    asm volatile("barrier.cluster.arrive.aligned;" ::: "memory");
}
__device__ __forceinline__ void cluster_wait_() {
    asm volatile("barrier.cluster.wait.aligned;" ::: "memory");
}

// overflow-safe fast sigmoid / tanh (MUFU-only)
__device__ __forceinline__ float sigmoid_(float x) {
    float e = __expf(-x);
    return __fdividef(1.0f, 1.0f + e);
}
__device__ __forceinline__ float tanh_(float x) {
    float e = __expf(2.0f * x);
    return 1.0f - __fdividef(2.0f, e + 1.0f);
}

__device__ __forceinline__ void mbar_init_(uint32_t addr, uint32_t cnt) {
    asm volatile("mbarrier.init.shared.b64 [%0], %1;" :: "r"(addr), "r"(cnt) : "memory");
}
__device__ __forceinline__ void mbar_arrive_expect_tx_(uint32_t addr, uint32_t bytes) {
    asm volatile("mbarrier.arrive.expect_tx.release.cta.shared::cta.b64 _, [%0], %1;"
                 :: "r"(addr), "r"(bytes) : "memory");
}
__device__ __forceinline__ void st_async_f32_(uint32_t dst, float v, uint32_t mbar) {
    asm volatile(
        "st.async.shared::cluster.mbarrier::complete_tx::bytes.f32 [%0], %1, [%2];"
        :: "r"(dst), "f"(v), "r"(mbar) : "memory");
}
__device__ __forceinline__ void bar_wait_(uint32_t mbar, uint32_t parity) {
    uint32_t done;
    asm volatile("{\n\t.reg .pred p;\n\t"
                 "mbarrier.try_wait.parity.acquire.cluster.shared::cta.b64 p, [%1], %2;\n\t"
                 "selp.b32 %0, 1, 0, p;\n\t}"
                 : "=r"(done) : "r"(mbar), "r"(parity) : "memory");
    while (!done) {
        asm volatile("{\n\t.reg .pred p;\n\t"
                     "mbarrier.try_wait.parity.acquire.cluster.shared::cta.b64 p, [%1], %2, 0x989680;\n\t"
                     "selp.b32 %0, 1, 0, p;\n\t}"
                     : "=r"(done) : "r"(mbar), "r"(parity) : "memory");
    }
}

// ---------------------------------------------------------------------------
// Kernel 1: xg = x @ W_i + bias    (M=65536, N=768, K=256)  fp32 tiled SGEMM
// REVERTED to the proven BM=128/BN=64/BK=16, 8x4 version (measured 677us;
// the 8x8 variant dropped occupancy 36.6->24.6% and regressed).
// ---------------------------------------------------------------------------
__global__ __launch_bounds__(256)
void gemm_xg_kernel(const float* __restrict__ X,
                    const float* __restrict__ Wi,
                    const float* __restrict__ bias)
{
    __shared__ __align__(16) float As[16][128];   // transposed A tile
    __shared__ __align__(16) float Bs[16][64];

    const int bm = blockIdx.x * 128;
    const int bn = blockIdx.y * 64;
    const int tid = threadIdx.x;
    const int tx = tid & 15;       // N direction (4 cols each)
    const int ty = tid >> 4;       // M direction (8 rows each)

    float acc[8][4];
#pragma unroll
    for (int i = 0; i < 8; ++i)
#pragma unroll
        for (int j = 0; j < 4; ++j) acc[i][j] = 0.0f;

    for (int k0 = 0; k0 < INDIM; k0 += 16) {
#pragma unroll
        for (int q = 0; q < 2; ++q) {
            int f   = q * 256 + tid;
            int row = f >> 2;
            int k4  = (f & 3) << 2;
            float4 v = *reinterpret_cast<const float4*>(
                X + (size_t)(bm + row) * INDIM + k0 + k4);
            As[k4 + 0][row] = v.x;
            As[k4 + 1][row] = v.y;
            As[k4 + 2][row] = v.z;
            As[k4 + 3][row] = v.w;
        }
        {
            int kr = tid >> 4;
            int c4 = (tid & 15) << 2;
            float4 v = *reinterpret_cast<const float4*>(
                Wi + (size_t)(k0 + kr) * GDIM + bn + c4);
            *reinterpret_cast<float4*>(&Bs[kr][c4]) = v;
        }
        __syncthreads();

#pragma unroll
        for (int kk = 0; kk < 16; ++kk) {
            float4 a0 = *reinterpret_cast<const float4*>(&As[kk][ty * 8]);
            float4 a1 = *reinterpret_cast<const float4*>(&As[kk][ty * 8 + 4]);
            float4 bv = *reinterpret_cast<const float4*>(&Bs[kk][tx * 4]);
            float a[8] = {a0.x, a0.y, a0.z, a0.w, a1.x, a1.y, a1.z, a1.w};
            float bb[4] = {bv.x, bv.y, bv.z, bv.w};
#pragma unroll
            for (int i = 0; i < 8; ++i)
#pragma unroll
                for (int j = 0; j < 4; ++j)
                    acc[i][j] = fmaf(a[i], bb[j], acc[i][j]);
        }
        __syncthreads();
    }

    float4 bv = *reinterpret_cast<const float4*>(bias + bn + tx * 4);
#pragma unroll
    for (int i = 0; i < 8; ++i) {
        int row = bm + ty * 8 + i;
        float4 o;
        o.x = acc[i][0] + bv.x;
        o.y = acc[i][1] + bv.y;
        o.z = acc[i][2] + bv.z;
        o.w = acc[i][3] + bv.w;
        *reinterpret_cast<float4*>(g_xg + (size_t)row * GDIM + bn + tx * 4) = o;
    }
}

// ---------------------------------------------------------------------------
// Kernel 2: GRU recurrence — R10's measured-best skeleton, with the
// barrier.cluster (UCGABAR ~490cyc + L1-flush/step) replaced by the
// st.async tx-counted mbarrier protocol:
//  - bars[2] (one per h buffer), init count=1, pre-armed expect_tx 1024B.
//  - gate threads st.async hn to all 4 ranks' h_sm[nxt] with complete_tx
//    to each rank's bars[nxt] (4 CTAs x 64 floats = 1024B per barrier/phase).
//  - all threads try_wait.parity.acquire (~60-90cyc wakeup, no flush);
//    tid0 re-arms bars[nxt] immediately after the wait (sole arrival).
// States STG + 2-deep xg prefetch sit between store-issue and wait.
// Grid = 128 CTAs, cluster of 4 per batch row, 384 threads/CTA.
// ---------------------------------------------------------------------------
__global__ __launch_bounds__(384, 1) __cluster_dims__(4, 1, 1)
void gru_rec_kernel(const float* __restrict__ Wh,
                    float* __restrict__ states)
{
    __shared__ __align__(16) float h_sm[2][HDIM];   // buf1 = buf0 + 1024B
    __shared__ __align__(16) float g_sm[192];
    __shared__ __align__(8) unsigned long long bars[2];

    uint32_t crank;
    asm("mov.u32 %0, %%cluster_ctarank;" : "=r"(crank));
    const int b      = blockIdx.x >> 2;
    const int tid    = threadIdx.x;
    const int half   = tid & 1;       // K half: [0,128) or [128,256)
    const int pairId = tid >> 1;      // 0..191
    const int gate   = pairId >> 6;   // 0..2
    const int jj     = pairId & 63;   // H index within chunk
    const int col    = gate * HDIM + (int)crank * 64 + jj;  // W_h column

    // ---- W half-column in 128 regs, granule order rotated by `half` ----
    float W[128];
    {
#pragma unroll
        for (int g = 0; g < 32; ++g) {
            int rho = (g + half) & 31;
            int kbase = half * 128 + rho * 4;
#pragma unroll
            for (int e = 0; e < 4; ++e)
                W[g * 4 + e] = Wh[(size_t)(kbase + e) * GDIM + col];
        }
    }

    // ---- init: h buffers, barriers (count=1, pre-armed both phases) ----
    if (tid < HDIM) { h_sm[0][tid] = 0.0f; h_sm[1][tid] = 0.0f; }
    const uint32_t bar_l0 = smem_u32(&bars[0]);    // bars[1] = +8B
    if (tid == 0) {
        mbar_init_(bar_l0, 1);
        mbar_init_(bar_l0 + 8u, 1);
        mbar_arrive_expect_tx_(bar_l0, 1024);       // arm first use of buf0
        mbar_arrive_expect_tx_(bar_l0 + 8u, 1024);  // arm first use of buf1
    }
    __syncthreads();
    cluster_arrive_();
    cluster_wait_();   // zeros + armed barriers visible cluster-wide

    // ---- gate threads (tid<64): remote h slot + barrier in all 4 ranks ----
    uint32_t dst0[4], rbar0[4];
    {
        uint32_t l0 = smem_u32(&h_sm[0][(int)crank * 64 + (tid & 63)]);
#pragma unroll
        for (int rk = 0; rk < 4; ++rk) {
            asm("mapa.shared::cluster.u32 %0, %1, %2;"
                : "=r"(dst0[rk]) : "r"(l0), "r"(rk));
            asm("mapa.shared::cluster.u32 %0, %1, %2;"
                : "=r"(rbar0[rk]) : "r"(bar_l0), "r"(rk));
        }
    }

    // ---- xg: 2-step-ahead register prefetch (gate threads) ----
    const float* xgp = g_xg + (size_t)b * TSTEPS * GDIM + (int)crank * 64 + (tid & 63);
    float x0r = 0.f, x0z = 0.f, x0n = 0.f;   // even t
    float x1r = 0.f, x1z = 0.f, x1n = 0.f;   // odd t
    if (tid < 64) {
        x0r = xgp[0];
        x0z = xgp[HDIM];
        x0n = xgp[2 * HDIM];
        const float* x1 = xgp + GDIM;
        x1r = x1[0];
        x1z = x1[HDIM];
        x1n = x1[2 * HDIM];
    }

    const size_t PL = (size_t)TSTEPS * HDIM;
    float* sp0 = states + (size_t)b * 4 * PL + (int)crank * 64 + (tid & 63);

    int ph0 = 0, ph1 = 0;   // parity per buffer barrier

    for (int t = 0; t < TSTEPS; ++t) {
        const int cur = t & 1;
        const int nxt = cur ^ 1;
        const bool last = (t == TSTEPS - 1);

        // gate threads: issue h_old load before the dot (hides LDS latency)
        float h_old = 0.f;
        if (tid < 64) h_old = h_sm[cur][(int)crank * 64 + tid];

        // ---- dot over my K half (rotated conflict-free LDS.128) ----
        const float4* hp = reinterpret_cast<const float4*>(&h_sm[cur][half * 128]);
        float a0 = 0.f, a1 = 0.f, a2 = 0.f, a3 = 0.f;
#pragma unroll
        for (int g = 0; g < 32; ++g) {
            int rho = (g + half) & 31;
            float4 hv = hp[rho];
            a0 = fmaf(W[g * 4 + 0], hv.x, a0);
            a1 = fmaf(W[g * 4 + 1], hv.y, a1);
            a2 = fmaf(W[g * 4 + 2], hv.z, a2);
            a3 = fmaf(W[g * 4 + 3], hv.w, a3);
        }
        float s = (a0 + a1) + (a2 + a3);
        s += __shfl_xor_sync(0xffffffffu, s, 1);   // combine the two halves

        if (half == 0) g_sm[pairId] = s;           // raw partial
        __syncthreads();                           // partials visible

        // ---- gates on 64 threads + st.async broadcast ----
        float r = 0.f, z = 0.f, n = 0.f, hn = 0.f;
        if (tid < 64) {
            float s0 = g_sm[tid];
            float s1 = g_sm[64 + tid];
            float s2 = g_sm[128 + tid];
            float xr = cur ? x1r : x0r;
            float xz = cur ? x1z : x0z;
            float xn = cur ? x1n : x0n;
            r  = sigmoid_(xr + s0);
            z  = sigmoid_(xz + s1);
            float gg = xn + s2;
            n  = tanh_(fmaf(r, gg, gg));           // tanh(gn + r*gn)
            hn = fmaf(z, h_old - n, n);            // (1-z)n + z h

            if (!last) {
                const uint32_t boff = (uint32_t)nxt * 1024u;  // h buffer offset
                const uint32_t soff = (uint32_t)nxt * 8u;     // barrier offset
#pragma unroll
                for (int rk = 0; rk < 4; ++rk)
                    st_async_f32_(dst0[rk] + boff, hn, rbar0[rk] + soff);
            }
        }

        // ---- overlapped with transit: states STG + xg prefetch (t+2) ----
        if (tid < 64) {
            float* sp = sp0 + (size_t)t * HDIM;
            sp[0]      = hn;
            sp[PL]     = r;
            sp[2 * PL] = z;
            sp[3 * PL] = n;
            if (t + 2 < TSTEPS) {
                const float* xq = xgp + (size_t)(t + 2) * GDIM;
                if (cur) { x1r = xq[0]; x1z = xq[HDIM]; x1n = xq[2 * HDIM]; }
                else     { x0r = xq[0]; x0z = xq[HDIM]; x0n = xq[2 * HDIM]; }
            }
        }

        if (!last) {
            // wait for all 1024B (4 CTAs x 64 floats) on buffer nxt
            if (nxt) { bar_wait_(bar_l0 + 8u, (uint32_t)ph1); ph1 ^= 1; }
            else     { bar_wait_(bar_l0,      (uint32_t)ph0); ph0 ^= 1; }
            // re-arm this barrier for its use 2 steps ahead (sole arrival;
            // >1000cyc margin before any phase-p+1 bytes can land)
            if (tid == 0) mbar_arrive_expect_tx_(bar_l0 + (uint32_t)nxt * 8u, 1024);
        }
    }
}

// ---------------------------------------------------------------------------
// Kernel 3: output = h_last @ fc_w + fc_b   (32 x 256, K=256) — tiny
// ---------------------------------------------------------------------------
__global__ __launch_bounds__(256)
void fc_kernel(const float* __restrict__ states,
               const float* __restrict__ fc_w,
               const float* __restrict__ fc_b,
               float* __restrict__ out)
{
    const int b = blockIdx.x;
    const int o = threadIdx.x;
    const float* h = states + (((size_t)b * 4 + 0) * TSTEPS + (TSTEPS - 1)) * HDIM;
    float a0 = 0.f, a1 = 0.f, a2 = 0.f, a3 = 0.f;
#pragma unroll 8
    for (int k = 0; k < HDIM; k += 4) {
        a0 = fmaf(h[k + 0], fc_w[(size_t)(k + 0) * OUTDIM + o], a0);
        a1 = fmaf(h[k + 1], fc_w[(size_t)(k + 1) * OUTDIM + o], a1);
        a2 = fmaf(h[k + 2], fc_w[(size_t)(k + 2) * OUTDIM + o], a2);
        a3 = fmaf(h[k + 3], fc_w[(size_t)(k + 3) * OUTDIM + o], a3);
    }
    out[(size_t)b * OUTDIM + o] = (a0 + a1) + (a2 + a3) + fc_b[o];
}

// ---------------------------------------------------------------------------
// Launch
// ---------------------------------------------------------------------------
extern "C" void kernel_launch(void* const* d_in, const int* in_sizes, int n_in,
                              void* d_out, int out_size)
{
    const float* x    = (const float*)d_in[0];
    const float* Wi   = (const float*)d_in[1];
    const float* Wh   = (const float*)d_in[2];
    const float* bias = (const float*)d_in[3];
    const float* fcw  = (const float*)d_in[4];
    const float* fcb  = (const float*)d_in[5];

    float* out    = (float*)d_out;                 // (32, 256)
    float* states = out + (size_t)BATCH * OUTDIM;  // (32, 4, 2048, 256)

    dim3 ggrid((BATCH * TSTEPS) / 128, GDIM / 64);
    gemm_xg_kernel<<<ggrid, 256>>>(x, Wi, bias);

    gru_rec_kernel<<<BATCH * 4, 384>>>(Wh, states);

    fc_kernel<<<BATCH, 256>>>(states, fcw, fcb, out);
}